// round 15
// baseline (speedup 1.0000x reference)
#include <cuda_runtime.h>
#include <cooperative_groups.h>
#include <math.h>
#include <stdint.h>

namespace cg = cooperative_groups;

#define NMAX 262144
#define NBANK 16
#define BSTRIDE 32   // doubles per bank (256B stride: no L2 hash pair-collide)

// ---------------- scratch ----------------------------------------------------
struct ScratchZ {
    float    h1[4 * NMAX];            // conv1 accum: h0, h1, cnt, pad
    double   stats1[NBANK * BSTRIDE]; // banked: [b]: s0,s1,sq0,sq1
    double   stats2[NBANK * BSTRIDE]; // banked: [b]: s0..s3, sq0..sq3
    unsigned done1, done2;            // last-block counters (fallback path only)
    unsigned pool[64];                // sign-aware ordered-uint, 0 == empty
};
__device__ ScratchZ g;
__device__ float    g_h2[4 * NMAX];
__device__ float    g_h1e[2 * NMAX];
__device__ float    g_inv[NMAX];
__device__ float    g_scale1[2], g_shift1[2];
__device__ float    g_scale2[4], g_shift2[4];

__device__ __forceinline__ unsigned fenc(float f) {
    unsigned u = __float_as_uint(f);
    return (u & 0x80000000u) ? ~u : (u | 0x80000000u);
}
__device__ __forceinline__ float fdec(unsigned u) {
    return (u & 0x80000000u) ? __uint_as_float(u & 0x7FFFFFFFu)
                             : __uint_as_float(~u);
}
#define REBASE 0x007FFFFFu

__device__ __forceinline__ void basis8(float f0, float f1, float f2, float* w) {
    float gr0 = 1.f - f0, gr1 = 1.f - f1, gr2 = 1.f - f2;
    float a00 = gr0 * gr1, a10 = f0 * gr1, a01 = gr0 * f1, a11 = f0 * f1;
    w[0] = a00 * gr2; w[1] = a10 * gr2; w[2] = a01 * gr2; w[3] = a11 * gr2;
    w[4] = a00 * f2;  w[5] = a10 * f2;  w[6] = a01 * f2;  w[7] = a11 * f2;
}

__device__ __forceinline__ int sniff64(const unsigned* w, int base, int E) {
    unsigned orv = 0;
#pragma unroll
    for (int i = 0; i < 8; i++) {
        int e = base + i;
        if (e < E) orv |= w[2 * e + 1];
    }
    return orv == 0u;
}

__device__ __forceinline__ void load_edge2(const void* eidx, int e, int E, int is64,
                                           int& sA, int& dA, int& sB, int& dB) {
    if (is64) {
        const longlong2* p = (const longlong2*)eidx;
        longlong2 s = __ldg(&p[e >> 1]);
        longlong2 d = __ldg(&p[(size_t)(E >> 1) + (e >> 1)]);
        sA = (int)s.x; sB = (int)s.y; dA = (int)d.x; dB = (int)d.y;
    } else {
        const int2* p = (const int2*)eidx;
        int2 s = __ldg(&p[e >> 1]);
        int2 d = __ldg(&p[(E >> 1) + (e >> 1)]);
        sA = s.x; sB = s.y; dA = d.x; dB = d.y;
    }
}
__device__ __forceinline__ void load_edge1(const void* eidx, int e, int E, int is64,
                                           int& src, int& dst) {
    if (is64) {
        const long long* p = (const long long*)eidx;
        src = (int)__ldg(&p[e]);
        dst = (int)__ldg(&p[(size_t)E + e]);
    } else {
        const int* p = (const int*)eidx;
        src = __ldg(&p[e]);
        dst = __ldg(&p[E + e]);
    }
}

__device__ __forceinline__ void stage_attr512(const float* __restrict__ attr,
                                              int base, int nEdge, float* sAttr) {
    int t = threadIdx.x;
    if (nEdge == 512) {
        const float4* a4 = (const float4*)attr;
        int g0 = (3 * base) >> 2;
#pragma unroll
        for (int i = 0; i < 2; i++) {
            int k = t + 256 * i;
            if (k < 384) *(float4*)&sAttr[4 * k] = __ldg(&a4[g0 + k]);
        }
    } else {
        for (int i = t; i < 3 * nEdge; i += 256)
            sAttr[i] = __ldg(&attr[3 * base + i]);
    }
    __syncthreads();
}

__device__ __forceinline__ void pair_attr(const float* sAttr, int t,
                                          float* fA, float* fB) {
    const float2* s2 = (const float2*)sAttr;
    float2 p0 = s2[3 * t], p1 = s2[3 * t + 1], p2 = s2[3 * t + 2];
    fA[0] = p0.x; fA[1] = p0.y; fA[2] = p1.x;
    fB[0] = p1.y; fB[1] = p2.x; fB[2] = p2.y;
}

// conv tile bodies ------------------------------------------------------------
__device__ __forceinline__ void conv1_tile(int tile, const float* x, const void* eidx,
                                           int E, int is64, const float2* sW,
                                           const float* attr, float* sAttr) {
    int t = threadIdx.x;
    int base = tile * 512;
    int nEdge = min(512, E - base);
    stage_attr512(attr, base, nEdge, sAttr);
    int le = 2 * t;
    if (le < nEdge) {
        int e = base + le;
        if (le + 1 < nEdge) {
            int sA, dA, sB, dB;
            load_edge2(eidx, e, E, is64, sA, dA, sB, dB);
            float xA = __ldg(&x[sA]);
            float xB = __ldg(&x[sB]);
            float fA[3], fB[3], w[8];
            pair_attr(sAttr, t, fA, fB);
            basis8(fA[0], fA[1], fA[2], w);
            float a0 = 0.f, a1 = 0.f;
#pragma unroll
            for (int b = 0; b < 8; b++) { float2 W = sW[b]; a0 = fmaf(w[b], W.x, a0); a1 = fmaf(w[b], W.y, a1); }
            a0 *= xA; a1 *= xA;
            asm volatile("red.global.add.v4.f32 [%0], {%1, %2, %3, %4};"
                         :: "l"(&g.h1[4 * dA]), "f"(a0), "f"(a1), "f"(1.0f), "f"(0.0f) : "memory");
            basis8(fB[0], fB[1], fB[2], w);
            float b0 = 0.f, b1 = 0.f;
#pragma unroll
            for (int b = 0; b < 8; b++) { float2 W = sW[b]; b0 = fmaf(w[b], W.x, b0); b1 = fmaf(w[b], W.y, b1); }
            b0 *= xB; b1 *= xB;
            asm volatile("red.global.add.v4.f32 [%0], {%1, %2, %3, %4};"
                         :: "l"(&g.h1[4 * dB]), "f"(b0), "f"(b1), "f"(1.0f), "f"(0.0f) : "memory");
        } else {
            int src, dst;
            load_edge1(eidx, e, E, is64, src, dst);
            float w[8];
            basis8(sAttr[3*le], sAttr[3*le+1], sAttr[3*le+2], w);
            float a0 = 0.f, a1 = 0.f;
#pragma unroll
            for (int b = 0; b < 8; b++) { float2 W = sW[b]; a0 = fmaf(w[b], W.x, a0); a1 = fmaf(w[b], W.y, a1); }
            float xs = __ldg(&x[src]);
            a0 *= xs; a1 *= xs;
            asm volatile("red.global.add.v4.f32 [%0], {%1, %2, %3, %4};"
                         :: "l"(&g.h1[4 * dst]), "f"(a0), "f"(a1), "f"(1.0f), "f"(0.0f) : "memory");
        }
    }
    __syncthreads();   // protect sAttr reuse across tiles
}

__device__ __forceinline__ void conv2_edge(float2 hv, int d, const float* f,
                                           const float4* sW, float sc0, float sh0,
                                           float sc1, float sh1) {
    float h0 = fmaf(hv.x, sc0, sh0);
    float h1 = fmaf(hv.y, sc1, sh1);
    float w[8];
    basis8(f[0], f[1], f[2], w);
    float acc0 = 0.f, acc1 = 0.f, acc2 = 0.f, acc3 = 0.f;
#pragma unroll
    for (int b = 0; b < 8; b++) {
        float4 A = sW[2 * b];
        float4 B = sW[2 * b + 1];
        float wb = w[b];
        acc0 = fmaf(wb, fmaf(h1, B.x, h0 * A.x), acc0);
        acc1 = fmaf(wb, fmaf(h1, B.y, h0 * A.y), acc1);
        acc2 = fmaf(wb, fmaf(h1, B.z, h0 * A.z), acc2);
        acc3 = fmaf(wb, fmaf(h1, B.w, h0 * A.w), acc3);
    }
    asm volatile("red.global.add.v4.f32 [%0], {%1, %2, %3, %4};"
                 :: "l"(&g_h2[4 * d]), "f"(acc0), "f"(acc1), "f"(acc2), "f"(acc3)
                 : "memory");
}

// ================= fused persistent cooperative kernel =======================
__global__ void __launch_bounds__(256, 6) k_fused(
        const float* __restrict__ x, const void* __restrict__ eidx,
        const float* __restrict__ attr, const float* __restrict__ pos,
        const float* __restrict__ W1, const float* __restrict__ W2,
        const float* __restrict__ gamma1, const float* __restrict__ beta1,
        const float* __restrict__ gamma2, const float* __restrict__ beta2,
        const float* __restrict__ fcw, float* __restrict__ out, int N, int E) {
    cg::grid_group grid = cg::this_grid();
    int t = threadIdx.x;
    int nblk = gridDim.x;
    long long gtid = (long long)blockIdx.x * 256 + t;
    long long gstr = (long long)nblk * 256;

    __shared__ float2 sW1[8];
    __shared__ float4 sW2[16];
    __shared__ __align__(16) float sAttr[1536];
    __shared__ float  wsum[8][8];
    __shared__ unsigned spool[64];
    __shared__ float  sP[12];    // sc1[2],sh1[2],sc2[4],sh2[4] staging

    // ---- P0: zero scratch ----
    float4 z4 = make_float4(0.f, 0.f, 0.f, 0.f);
    for (long long i = gtid; i < N; i += gstr) {
        *(float4*)&g.h1[4 * i] = z4;
        *(float4*)&g_h2[4 * i] = z4;
    }
    if (blockIdx.x == 0) {
        for (int i = t; i < NBANK * BSTRIDE; i += 256) { g.stats1[i] = 0.0; g.stats2[i] = 0.0; }
        if (t < 64) g.pool[t] = 0u;
    }
    if (t < 8)  sW1[t] = ((const float2*)W1)[t];
    if (t < 16) sW2[t] = ((const float4*)W2)[t];
    int is64 = sniff64((const unsigned*)eidx, 0, E);
    grid.sync();

    // ---- P1: conv1 ----
    int etiles = (E + 511) / 512;
    for (int tile = blockIdx.x; tile < etiles; tile += nblk)
        conv1_tile(tile, x, eidx, E, is64, sW1, attr, sAttr);
    grid.sync();

    // ---- P2: finish1 (mean->ELU->h1e, inv; stats1 accumulate) ----
    {
        float s0 = 0.f, s1 = 0.f, s2 = 0.f, s3 = 0.f;
        for (long long n = gtid; n < N; n += gstr) {
            float4 h  = *(const float4*)&g.h1[4 * n];
            float inv = 1.0f / fmaxf(h.z, 1.0f);
            g_inv[n] = inv;
            float a = h.x * inv, b = h.y * inv;
            a = (a > 0.f) ? a : expm1f(a);
            b = (b > 0.f) ? b : expm1f(b);
            *(float2*)&g_h1e[2 * n] = make_float2(a, b);
            s0 += a; s1 += b; s2 += a * a; s3 += b * b;
        }
#pragma unroll
        for (int o = 16; o; o >>= 1) {
            s0 += __shfl_down_sync(~0u, s0, o);
            s1 += __shfl_down_sync(~0u, s1, o);
            s2 += __shfl_down_sync(~0u, s2, o);
            s3 += __shfl_down_sync(~0u, s3, o);
        }
        if ((t & 31) == 0) {
            int wid = t >> 5;
            wsum[wid][0] = s0; wsum[wid][1] = s1; wsum[wid][2] = s2; wsum[wid][3] = s3;
        }
        __syncthreads();
        if (t < 4) {
            double acc = 0.0;
#pragma unroll
            for (int w = 0; w < 8; w++) acc += (double)wsum[w][t];
            atomicAdd(&g.stats1[(blockIdx.x & (NBANK - 1)) * BSTRIDE + t], acc);
        }
    }
    grid.sync();

    // ---- BN1 params: computed redundantly per block ----
    if (t < 2) {
        double sum = 0.0, sumsq = 0.0;
#pragma unroll
        for (int bk = 0; bk < NBANK; bk++) {
            sum   += g.stats1[bk * BSTRIDE + t];
            sumsq += g.stats1[bk * BSTRIDE + 2 + t];
        }
        double invN = 1.0 / (double)N;
        double mu   = sum * invN;
        double var  = sumsq * invN - mu * mu;
        float  sc   = (float)((double)__ldg(&gamma1[t]) / sqrt(var + 1e-5));
        sP[t]     = sc;
        sP[2 + t] = __ldg(&beta1[t]) - (float)mu * sc;
    }
    __syncthreads();
    float sc0 = sP[0], sc1v = sP[1], sh0 = sP[2], sh1v = sP[3];

    // ---- P3: conv2 ----
    for (int tile = blockIdx.x; tile < etiles; tile += nblk) {
        int base = tile * 512;
        int nEdge = min(512, E - base);
        stage_attr512(attr, base, nEdge, sAttr);
        int le = 2 * t;
        if (le < nEdge) {
            int e = base + le;
            if (le + 1 < nEdge) {
                int sA, dA, sB, dB;
                load_edge2(eidx, e, E, is64, sA, dA, sB, dB);
                float2 hA = *(const float2*)&g_h1e[2 * sA];
                float2 hB = *(const float2*)&g_h1e[2 * sB];
                float fA[3], fB[3];
                pair_attr(sAttr, t, fA, fB);
                conv2_edge(hA, dA, fA, sW2, sc0, sh0, sc1v, sh1v);
                conv2_edge(hB, dB, fB, sW2, sc0, sh0, sc1v, sh1v);
            } else {
                int src, dst;
                load_edge1(eidx, e, E, is64, src, dst);
                float2 hv = *(const float2*)&g_h1e[2 * src];
                float f[3] = {sAttr[3*le], sAttr[3*le+1], sAttr[3*le+2]};
                conv2_edge(hv, dst, f, sW2, sc0, sh0, sc1v, sh1v);
            }
        }
        __syncthreads();
    }
    grid.sync();

    // ---- P4: finish2 (mean, pool, stats2) ----
    {
        unsigned neg = 0;
#pragma unroll
        for (int o = 0; o < 4; o++)
            if (__ldg(&gamma2[o]) < 0.f) neg |= 1u << o;
        if (t < 64) spool[t] = 0u;
        __syncthreads();
        float s[8] = {0.f,0.f,0.f,0.f,0.f,0.f,0.f,0.f};
        for (long long n = gtid; n < N; n += gstr) {
            float4 h  = *(const float4*)&g_h2[4 * n];
            float inv = g_inv[n];
            float m0 = h.x * inv, m1 = h.y * inv, m2 = h.z * inv, m3 = h.w * inv;
            float2 p = *(const float2*)&pos[2 * n];
            int cx = min(max((int)floorf(p.x * 0.04f), 0), 3);
            int cy = min(max((int)floorf(p.y * 0.04f), 0), 3);
            int cl = 4 * (cx + 4 * cy);
            unsigned e0 = fenc(m0), e1 = fenc(m1), e2 = fenc(m2), e3 = fenc(m3);
            atomicMax(&spool[cl + 0], (neg & 1u) ? ~e0 : (e0 - REBASE));
            atomicMax(&spool[cl + 1], (neg & 2u) ? ~e1 : (e1 - REBASE));
            atomicMax(&spool[cl + 2], (neg & 4u) ? ~e2 : (e2 - REBASE));
            atomicMax(&spool[cl + 3], (neg & 8u) ? ~e3 : (e3 - REBASE));
            s[0] += m0; s[1] += m1; s[2] += m2; s[3] += m3;
            s[4] += m0 * m0; s[5] += m1 * m1; s[6] += m2 * m2; s[7] += m3 * m3;
        }
#pragma unroll
        for (int o = 16; o; o >>= 1)
#pragma unroll
            for (int k = 0; k < 8; k++) s[k] += __shfl_down_sync(~0u, s[k], o);
        if ((t & 31) == 0) {
            int wid = t >> 5;
#pragma unroll
            for (int k = 0; k < 8; k++) wsum[wid][k] = s[k];
        }
        __syncthreads();
        if (t < 8) {
            double acc = 0.0;
#pragma unroll
            for (int w = 0; w < 8; w++) acc += (double)wsum[w][t];
            atomicAdd(&g.stats2[(blockIdx.x & (NBANK - 1)) * BSTRIDE + t], acc);
        }
        if (t < 64 && spool[t]) atomicMax(&g.pool[t], spool[t]);
    }
    grid.sync();

    // ---- P5: block 0 computes BN2 + fc ----
    if (blockIdx.x == 0) {
        unsigned neg = 0;
#pragma unroll
        for (int o = 0; o < 4; o++)
            if (__ldg(&gamma2[o]) < 0.f) neg |= 1u << o;
        if (t < 4) {
            double sum = 0.0, sumsq = 0.0;
#pragma unroll
            for (int bk = 0; bk < NBANK; bk++) {
                sum   += g.stats2[bk * BSTRIDE + t];
                sumsq += g.stats2[bk * BSTRIDE + 4 + t];
            }
            double invN = 1.0 / (double)N;
            double mu   = sum * invN;
            double var  = sumsq * invN - mu * mu;
            float  sc   = (float)((double)__ldg(&gamma2[t]) / sqrt(var + 1e-5));
            sP[4 + t] = sc;
            sP[8 + t] = __ldg(&beta2[t]) - (float)mu * sc;
        }
        __syncthreads();
        __shared__ float v[64];
        if (t < 64) {
            int      o   = t & 3;
            unsigned e   = g.pool[t];
            float    val = (neg >> o & 1) ? fdec(~e) : fdec(e + REBASE);
            v[t] = (e == 0u) ? 0.0f : fmaf(val, sP[4 + o], sP[8 + o]);
        }
        __syncthreads();
        if (t < 128) {
            int w = t >> 5, l = t & 31;
            float p = v[l] * fcw[w * 64 + l] + v[l + 32] * fcw[w * 64 + l + 32];
#pragma unroll
            for (int o = 16; o; o >>= 1) p += __shfl_down_sync(~0u, p, o);
            if (l == 0) out[w] = p;
        }
    }
}

// ================= fallback 4-kernel path (proven R13 structure) =============
__global__ void __launch_bounds__(256) k_conv1(
        const float* __restrict__ x, const void* __restrict__ eidx,
        const float* __restrict__ attr, const float* __restrict__ W1, int E) {
    __shared__ float2 sW[8];
    __shared__ __align__(16) float sAttr[1536];
    int t = threadIdx.x;
    int base = blockIdx.x * 512;
    if (t < 8) sW[t] = ((const float2*)W1)[t];
    int is64 = sniff64((const unsigned*)eidx, base, E);
    int nEdge = min(512, E - base);
    stage_attr512(attr, base, nEdge, sAttr);
    int le = 2 * t;
    if (le >= nEdge) return;
    int e = base + le;
    if (le + 1 < nEdge) {
        int sA, dA, sB, dB;
        load_edge2(eidx, e, E, is64, sA, dA, sB, dB);
        float xA = __ldg(&x[sA]);
        float xB = __ldg(&x[sB]);
        float fA[3], fB[3], w[8];
        pair_attr(sAttr, t, fA, fB);
        basis8(fA[0], fA[1], fA[2], w);
        float a0 = 0.f, a1 = 0.f;
#pragma unroll
        for (int b = 0; b < 8; b++) { float2 W = sW[b]; a0 = fmaf(w[b], W.x, a0); a1 = fmaf(w[b], W.y, a1); }
        a0 *= xA; a1 *= xA;
        asm volatile("red.global.add.v4.f32 [%0], {%1, %2, %3, %4};"
                     :: "l"(&g.h1[4 * dA]), "f"(a0), "f"(a1), "f"(1.0f), "f"(0.0f) : "memory");
        basis8(fB[0], fB[1], fB[2], w);
        float b0 = 0.f, b1 = 0.f;
#pragma unroll
        for (int b = 0; b < 8; b++) { float2 W = sW[b]; b0 = fmaf(w[b], W.x, b0); b1 = fmaf(w[b], W.y, b1); }
        b0 *= xB; b1 *= xB;
        asm volatile("red.global.add.v4.f32 [%0], {%1, %2, %3, %4};"
                     :: "l"(&g.h1[4 * dB]), "f"(b0), "f"(b1), "f"(1.0f), "f"(0.0f) : "memory");
    } else {
        int src, dst;
        load_edge1(eidx, e, E, is64, src, dst);
        float w[8];
        basis8(sAttr[3*le], sAttr[3*le+1], sAttr[3*le+2], w);
        float a0 = 0.f, a1 = 0.f;
#pragma unroll
        for (int b = 0; b < 8; b++) { float2 W = sW[b]; a0 = fmaf(w[b], W.x, a0); a1 = fmaf(w[b], W.y, a1); }
        float xs = __ldg(&x[src]);
        a0 *= xs; a1 *= xs;
        asm volatile("red.global.add.v4.f32 [%0], {%1, %2, %3, %4};"
                     :: "l"(&g.h1[4 * dst]), "f"(a0), "f"(a1), "f"(1.0f), "f"(0.0f) : "memory");
    }
}

__global__ void __launch_bounds__(256) k_finish1(
        const float* __restrict__ gamma1, const float* __restrict__ beta1, int N) {
    __shared__ float wsum[8][4];
    int t = threadIdx.x;
    int base = blockIdx.x * 1024;
    float s0 = 0.f, s1 = 0.f, s2 = 0.f, s3 = 0.f;
#pragma unroll
    for (int k = 0; k < 4; k++) {
        int n = base + t + 256 * k;
        if (n < N) {
            float4 h  = *(const float4*)&g.h1[4 * n];
            *(float4*)&g_h2[4 * n] = make_float4(0.f, 0.f, 0.f, 0.f);
            float inv = 1.0f / fmaxf(h.z, 1.0f);
            g_inv[n] = inv;
            float a = h.x * inv, b = h.y * inv;
            a = (a > 0.f) ? a : expm1f(a);
            b = (b > 0.f) ? b : expm1f(b);
            *(float2*)&g_h1e[2 * n] = make_float2(a, b);
            s0 += a; s1 += b; s2 += a * a; s3 += b * b;
        }
    }
#pragma unroll
    for (int o = 16; o; o >>= 1) {
        s0 += __shfl_down_sync(~0u, s0, o);
        s1 += __shfl_down_sync(~0u, s1, o);
        s2 += __shfl_down_sync(~0u, s2, o);
        s3 += __shfl_down_sync(~0u, s3, o);
    }
    if ((t & 31) == 0) {
        int wid = t >> 5;
        wsum[wid][0] = s0; wsum[wid][1] = s1; wsum[wid][2] = s2; wsum[wid][3] = s3;
    }
    __syncthreads();
    if (t < 4) {
        double acc = 0.0;
#pragma unroll
        for (int w = 0; w < 8; w++) acc += (double)wsum[w][t];
        atomicAdd(&g.stats1[(blockIdx.x & (NBANK - 1)) * BSTRIDE + t], acc);
    }
    __shared__ int last;
    __syncthreads();
    if (t == 0) {
        __threadfence();
        last = (atomicAdd(&g.done1, 1u) == gridDim.x - 1);
    }
    __syncthreads();
    if (last && t < 2) {
        __threadfence();
        double sum = 0.0, sumsq = 0.0;
#pragma unroll
        for (int bk = 0; bk < NBANK; bk++) {
            sum   += g.stats1[bk * BSTRIDE + t];
            sumsq += g.stats1[bk * BSTRIDE + 2 + t];
        }
        double invN = 1.0 / (double)N;
        double mu   = sum * invN;
        double var  = sumsq * invN - mu * mu;
        float  sc   = (float)((double)gamma1[t] / sqrt(var + 1e-5));
        g_scale1[t] = sc;
        g_shift1[t] = beta1[t] - (float)mu * sc;
    }
}

__global__ void __launch_bounds__(256) k_conv2(
        const void* __restrict__ eidx, const float* __restrict__ attr,
        const float* __restrict__ W2, int E) {
    __shared__ float4 sW[16];
    __shared__ __align__(16) float sAttr[1536];
    __shared__ float  sSc[2], sSh[2];
    int t = threadIdx.x;
    int base = blockIdx.x * 512;
    if (t < 16) sW[t] = ((const float4*)W2)[t];
    if (t < 2)  { sSc[t] = g_scale1[t]; sSh[t] = g_shift1[t]; }
    int is64 = sniff64((const unsigned*)eidx, base, E);
    int nEdge = min(512, E - base);
    stage_attr512(attr, base, nEdge, sAttr);
    int le = 2 * t;
    if (le >= nEdge) return;
    int e = base + le;
    if (le + 1 < nEdge) {
        int sA, dA, sB, dB;
        load_edge2(eidx, e, E, is64, sA, dA, sB, dB);
        float2 hA = *(const float2*)&g_h1e[2 * sA];
        float2 hB = *(const float2*)&g_h1e[2 * sB];
        float fA[3], fB[3];
        pair_attr(sAttr, t, fA, fB);
        conv2_edge(hA, dA, fA, sW, sSc[0], sSh[0], sSc[1], sSh[1]);
        conv2_edge(hB, dB, fB, sW, sSc[0], sSh[0], sSc[1], sSh[1]);
    } else {
        int src, dst;
        load_edge1(eidx, e, E, is64, src, dst);
        float2 hv = *(const float2*)&g_h1e[2 * src];
        float f[3] = {sAttr[3*le], sAttr[3*le+1], sAttr[3*le+2]};
        conv2_edge(hv, dst, f, sW, sSc[0], sSh[0], sSc[1], sSh[1]);
    }
}

__global__ void __launch_bounds__(256) k_finish2(
        const float* __restrict__ pos,
        const float* __restrict__ gamma2, const float* __restrict__ beta2,
        const float* __restrict__ fcw, float* __restrict__ out, int N) {
    __shared__ unsigned spool[64];
    __shared__ float    wsum[8][8];
    __shared__ unsigned sNeg;
    int t = threadIdx.x;
    if (t < 64) spool[t] = 0u;
    if (t == 0) {
        unsigned mk = 0;
#pragma unroll
        for (int o = 0; o < 4; o++)
            if (__ldg(&gamma2[o]) < 0.f) mk |= 1u << o;
        sNeg = mk;
    }
    __syncthreads();
    unsigned neg = sNeg;
    int base = blockIdx.x * 1024;
    float s[8] = {0.f,0.f,0.f,0.f,0.f,0.f,0.f,0.f};
#pragma unroll
    for (int k = 0; k < 4; k++) {
        int n = base + t + 256 * k;
        if (n < N) {
            float4 h  = *(const float4*)&g_h2[4 * n];
            float inv = g_inv[n];
            float m0 = h.x * inv, m1 = h.y * inv, m2 = h.z * inv, m3 = h.w * inv;
            float2 p = *(const float2*)&pos[2 * n];
            int cx = min(max((int)floorf(p.x * 0.04f), 0), 3);
            int cy = min(max((int)floorf(p.y * 0.04f), 0), 3);
            int cl = 4 * (cx + 4 * cy);
            unsigned e0 = fenc(m0), e1 = fenc(m1), e2 = fenc(m2), e3 = fenc(m3);
            atomicMax(&spool[cl + 0], (neg & 1u) ? ~e0 : (e0 - REBASE));
            atomicMax(&spool[cl + 1], (neg & 2u) ? ~e1 : (e1 - REBASE));
            atomicMax(&spool[cl + 2], (neg & 4u) ? ~e2 : (e2 - REBASE));
            atomicMax(&spool[cl + 3], (neg & 8u) ? ~e3 : (e3 - REBASE));
            s[0] += m0; s[1] += m1; s[2] += m2; s[3] += m3;
            s[4] += m0 * m0; s[5] += m1 * m1; s[6] += m2 * m2; s[7] += m3 * m3;
        }
    }
#pragma unroll
    for (int o = 16; o; o >>= 1)
#pragma unroll
        for (int k = 0; k < 8; k++) s[k] += __shfl_down_sync(~0u, s[k], o);
    if ((t & 31) == 0) {
        int wid = t >> 5;
#pragma unroll
        for (int k = 0; k < 8; k++) wsum[wid][k] = s[k];
    }
    __syncthreads();
    if (t < 8) {
        double acc = 0.0;
#pragma unroll
        for (int w = 0; w < 8; w++) acc += (double)wsum[w][t];
        atomicAdd(&g.stats2[(blockIdx.x & (NBANK - 1)) * BSTRIDE + t], acc);
    }
    if (t < 64 && spool[t]) atomicMax(&g.pool[t], spool[t]);
    __shared__ int last;
    __syncthreads();
    if (t == 0) {
        __threadfence();
        last = (atomicAdd(&g.done2, 1u) == gridDim.x - 1);
    }
    __syncthreads();
    if (!last) return;
    if (t < 4) {
        __threadfence();
        double sum = 0.0, sumsq = 0.0;
#pragma unroll
        for (int bk = 0; bk < NBANK; bk++) {
            sum   += g.stats2[bk * BSTRIDE + t];
            sumsq += g.stats2[bk * BSTRIDE + 4 + t];
        }
        double invN = 1.0 / (double)N;
        double mu   = sum * invN;
        double var  = sumsq * invN - mu * mu;
        float  sc   = (float)((double)gamma2[t] / sqrt(var + 1e-5));
        g_scale2[t] = sc;
        g_shift2[t] = beta2[t] - (float)mu * sc;
    }
    __syncthreads();
    __shared__ float v[64];
    if (t < 64) {
        int      o   = t & 3;
        unsigned e   = g.pool[t];
        float    val = (neg >> o & 1) ? fdec(~e) : fdec(e + REBASE);
        v[t] = (e == 0u) ? 0.0f : fmaf(val, g_scale2[o], g_shift2[o]);
    }
    __syncthreads();
    if (t < 128) {
        int w = t >> 5, l = t & 31;
        float p = v[l] * fcw[w * 64 + l] + v[l + 32] * fcw[w * 64 + l + 32];
#pragma unroll
        for (int o = 16; o; o >>= 1) p += __shfl_down_sync(~0u, p, o);
        if (l == 0) out[w] = p;
    }
}

// ---------------- host launcher ----------------------------------------------
extern "C" void kernel_launch(void* const* d_in, const int* in_sizes, int n_in,
                              void* d_out, int out_size) {
    const float* x      = (const float*)d_in[0];
    const void*  eidx   = d_in[1];
    const float* attr   = (const float*)d_in[2];
    const float* pos    = (const float*)d_in[3];
    const float* W1     = (const float*)d_in[4];
    const float* W2     = (const float*)d_in[5];
    const float* gamma1 = (const float*)d_in[6];
    const float* beta1  = (const float*)d_in[7];
    const float* gamma2 = (const float*)d_in[8];
    const float* beta2  = (const float*)d_in[9];
    const float* fcw    = (const float*)d_in[10];
    float*       out    = (float*)d_out;

    int N = in_sizes[0];        // x is [N,1]
    int E = in_sizes[2] / 3;    // edge_attr is [E,3]

    // cooperative grid sizing (host-side queries; no allocation)
    static int coopGrid = -2;   // -2 = uninit, -1 = unsupported
    if (coopGrid == -2) {
        int dev = 0, sms = 0, coop = 0, maxb = 0;
        cudaGetDevice(&dev);
        cudaDeviceGetAttribute(&coop, cudaDevAttrCooperativeLaunch, dev);
        cudaDeviceGetAttribute(&sms, cudaDevAttrMultiProcessorCount, dev);
        if (coop &&
            cudaOccupancyMaxActiveBlocksPerMultiprocessor(&maxb, k_fused, 256, 0)
                == cudaSuccess && maxb > 0)
            coopGrid = sms * maxb;
        else
            coopGrid = -1;
    }

    if (coopGrid > 0) {
        void* args[] = {(void*)&x, (void*)&eidx, (void*)&attr, (void*)&pos,
                        (void*)&W1, (void*)&W2, (void*)&gamma1, (void*)&beta1,
                        (void*)&gamma2, (void*)&beta2, (void*)&fcw, (void*)&out,
                        (void*)&N, (void*)&E};
        cudaError_t err = cudaLaunchCooperativeKernel(
            (const void*)k_fused, dim3(coopGrid), dim3(256), args, 0, (cudaStream_t)0);
        if (err == cudaSuccess) return;
        cudaGetLastError();     // clear; fall through to 4-kernel path
        coopGrid = -1;
    }

    // fallback: proven 4-kernel path
    void* pg;
    cudaGetSymbolAddress(&pg, g);
    cudaMemsetAsync(pg, 0, sizeof(ScratchZ));
    int ebl  = (E + 511) / 512;
    int nbl4 = (N + 1023) / 1024;
    k_conv1<<<ebl, 256>>>(x, eidx, attr, W1, E);
    k_finish1<<<nbl4, 256>>>(gamma1, beta1, N);
    k_conv2<<<ebl, 256>>>(eidx, attr, W2, E);
    k_finish2<<<nbl4, 256>>>(pos, gamma2, beta2, fcw, out, N);
}

// round 16
// speedup vs baseline: 1.2499x; 1.2499x over previous
#include <cuda_runtime.h>
#include <math.h>
#include <stdint.h>

#define NMAX 262144
#define NBANK 16
#define BSTRIDE 32   // doubles per bank (256B stride: no L2 hash pair-collide)

// ---------------- scratch (device globals; single zero-memset) ---------------
struct ScratchT {
    float    h1[4 * NMAX];            // conv1 accum: h0, h1, cnt, pad
    float    h2[4 * NMAX];            // conv2 accum: 4 channels
    double   stats1[NBANK * BSTRIDE]; // banked: [b]: s0,s1,sq0,sq1
    double   stats2[NBANK * BSTRIDE]; // banked: [b]: s0..s3, sq0..sq3
    unsigned done1, done2;            // last-block counters
    unsigned pool[64];                // sign-aware ordered-uint, 0 == empty
};
__device__ ScratchT g;
__device__ float    g_h1e[2 * NMAX];  // elu(mean(h1)) packed float2
__device__ float    g_inv[NMAX];      // 1 / max(cnt,1)
__device__ float    g_scale1[2], g_shift1[2];
__device__ float    g_scale2[4], g_shift2[4];

// ordered-uint encoding: unsigned compare == float compare
__device__ __forceinline__ unsigned fenc(float f) {
    unsigned u = __float_as_uint(f);
    return (u & 0x80000000u) ? ~u : (u | 0x80000000u);
}
__device__ __forceinline__ float fdec(unsigned u) {
    return (u & 0x80000000u) ? __uint_as_float(u & 0x7FFFFFFFu)
                             : __uint_as_float(~u);
}
#define REBASE 0x007FFFFFu   // fenc(-inf): re-base so 0 marks "empty"

// ---------------- trilinear basis weights (pseudo in [0,1): lo==0) -----------
__device__ __forceinline__ void basis8(float f0, float f1, float f2, float* w) {
    float gr0 = 1.f - f0, gr1 = 1.f - f1, gr2 = 1.f - f2;
    float a00 = gr0 * gr1, a10 = f0 * gr1, a01 = gr0 * f1, a11 = f0 * f1;
    w[0] = a00 * gr2; w[1] = a10 * gr2; w[2] = a01 * gr2; w[3] = a11 * gr2;
    w[4] = a00 * f2;  w[5] = a10 * f2;  w[6] = a01 * f2;  w[7] = a11 * f2;
}

// per-block idx-dtype sniff: odd 32-bit words all zero over 8 samples => int64
__device__ __forceinline__ int sniff64(const unsigned* w, int base, int E) {
    unsigned orv = 0;
#pragma unroll
    for (int i = 0; i < 8; i++) {
        int e = base + i;
        if (e < E) orv |= w[2 * e + 1];
    }
    return orv == 0u;
}

// paired index load for edges (e, e+1), e even
__device__ __forceinline__ void load_edge2(const void* eidx, int e, int E, int is64,
                                           int& sA, int& dA, int& sB, int& dB) {
    if (is64) {
        const longlong2* p = (const longlong2*)eidx;
        longlong2 s = __ldg(&p[e >> 1]);
        longlong2 d = __ldg(&p[(size_t)(E >> 1) + (e >> 1)]);
        sA = (int)s.x; sB = (int)s.y; dA = (int)d.x; dB = (int)d.y;
    } else {
        const int2* p = (const int2*)eidx;
        int2 s = __ldg(&p[e >> 1]);
        int2 d = __ldg(&p[(E >> 1) + (e >> 1)]);
        sA = s.x; sB = s.y; dA = d.x; dB = d.y;
    }
}
__device__ __forceinline__ void load_edge1(const void* eidx, int e, int E, int is64,
                                           int& src, int& dst) {
    if (is64) {
        const long long* p = (const long long*)eidx;
        src = (int)__ldg(&p[e]);
        dst = (int)__ldg(&p[(size_t)E + e]);
    } else {
        const int* p = (const int*)eidx;
        src = __ldg(&p[e]);
        dst = __ldg(&p[E + e]);
    }
}

// stage 512 edges' attr (1536 floats) into smem via coalesced float4 loads
__device__ __forceinline__ void stage_attr512(const float* __restrict__ attr,
                                              int base, int nEdge, float* sAttr) {
    int t = threadIdx.x;
    if (nEdge == 512) {
        const float4* a4 = (const float4*)attr;
        int g0 = (3 * base) >> 2;
#pragma unroll
        for (int i = 0; i < 2; i++) {
            int k = t + 256 * i;
            if (k < 384) *(float4*)&sAttr[4 * k] = __ldg(&a4[g0 + k]);
        }
    } else {
        for (int i = t; i < 3 * nEdge; i += 256)
            sAttr[i] = __ldg(&attr[3 * base + i]);
    }
    __syncthreads();
}

// read edge-pair attr via 3x LDS.64
__device__ __forceinline__ void pair_attr(const float* sAttr, int t,
                                          float* fA, float* fB) {
    const float2* s2 = (const float2*)sAttr;
    float2 p0 = s2[3 * t], p1 = s2[3 * t + 1], p2 = s2[3 * t + 2];
    fA[0] = p0.x; fA[1] = p0.y; fA[2] = p1.x;
    fB[0] = p1.y; fB[1] = p2.x; fB[2] = p2.y;
}

// ---------------- conv1: x[N,1] x W1 -> red.v4 (h0,h1,cnt,0), 2 edges/thr ----
// shared-weight loop: each sW[b] load feeds BOTH edges (8 LDS.64 vs 16)
__global__ void __launch_bounds__(256) k_conv1(
        const float* __restrict__ x, const void* __restrict__ eidx,
        const float* __restrict__ attr, const float* __restrict__ W1, int E) {
    __shared__ float2 sW[8];
    __shared__ __align__(16) float sAttr[1536];
    __shared__ int    sI64;
    int t = threadIdx.x;
    int base = blockIdx.x * 512;
    if (t < 8) sW[t] = ((const float2*)W1)[t];
    if (t == 0) sI64 = sniff64((const unsigned*)eidx, base, E);
    int nEdge = min(512, E - base);
    stage_attr512(attr, base, nEdge, sAttr);

    int le = 2 * t;
    if (le >= nEdge) return;
    int e = base + le;

    if (le + 1 < nEdge) {
        int sA, dA, sB, dB;
        load_edge2(eidx, e, E, sI64, sA, dA, sB, dB);
        float xA = __ldg(&x[sA]);
        float xB = __ldg(&x[sB]);
        float fA[3], fB[3], wA[8], wB[8];
        pair_attr(sAttr, t, fA, fB);
        basis8(fA[0], fA[1], fA[2], wA);
        basis8(fB[0], fB[1], fB[2], wB);
        float a0 = 0.f, a1 = 0.f, b0 = 0.f, b1 = 0.f;
#pragma unroll
        for (int b = 0; b < 8; b++) {
            float2 W = sW[b];                 // one load, two edges
            a0 = fmaf(wA[b], W.x, a0); a1 = fmaf(wA[b], W.y, a1);
            b0 = fmaf(wB[b], W.x, b0); b1 = fmaf(wB[b], W.y, b1);
        }
        a0 *= xA; a1 *= xA; b0 *= xB; b1 *= xB;
        asm volatile("red.global.add.v4.f32 [%0], {%1, %2, %3, %4};"
                     :: "l"(&g.h1[4 * dA]), "f"(a0), "f"(a1), "f"(1.0f), "f"(0.0f) : "memory");
        asm volatile("red.global.add.v4.f32 [%0], {%1, %2, %3, %4};"
                     :: "l"(&g.h1[4 * dB]), "f"(b0), "f"(b1), "f"(1.0f), "f"(0.0f) : "memory");
    } else {
        int src, dst;
        load_edge1(eidx, e, E, sI64, src, dst);
        float w[8];
        basis8(sAttr[3*le], sAttr[3*le+1], sAttr[3*le+2], w);
        float a0 = 0.f, a1 = 0.f;
#pragma unroll
        for (int b = 0; b < 8; b++) { float2 W = sW[b]; a0 = fmaf(w[b], W.x, a0); a1 = fmaf(w[b], W.y, a1); }
        float xs = __ldg(&x[src]);
        a0 *= xs; a1 *= xs;
        asm volatile("red.global.add.v4.f32 [%0], {%1, %2, %3, %4};"
                     :: "l"(&g.h1[4 * dst]), "f"(a0), "f"(a1), "f"(1.0f), "f"(0.0f) : "memory");
    }
}

// ---------------- finish1: 4 nodes/thread, mean->ELU->store, BN1 stats -------
__global__ void __launch_bounds__(256) k_finish1(
        const float* __restrict__ gamma1, const float* __restrict__ beta1, int N) {
    __shared__ float wsum[8][4];
    int t = threadIdx.x;
    int base = blockIdx.x * 1024;
    float s0 = 0.f, s1 = 0.f, s2 = 0.f, s3 = 0.f;
#pragma unroll
    for (int k = 0; k < 4; k++) {
        int n = base + t + 256 * k;
        if (n < N) {
            float4 h  = *(const float4*)&g.h1[4 * n];
            float inv = 1.0f / fmaxf(h.z, 1.0f);
            g_inv[n] = inv;
            float a = h.x * inv, b = h.y * inv;
            a = (a > 0.f) ? a : expm1f(a);
            b = (b > 0.f) ? b : expm1f(b);
            *(float2*)&g_h1e[2 * n] = make_float2(a, b);
            s0 += a; s1 += b; s2 += a * a; s3 += b * b;
        }
    }
#pragma unroll
    for (int o = 16; o; o >>= 1) {
        s0 += __shfl_down_sync(~0u, s0, o);
        s1 += __shfl_down_sync(~0u, s1, o);
        s2 += __shfl_down_sync(~0u, s2, o);
        s3 += __shfl_down_sync(~0u, s3, o);
    }
    if ((t & 31) == 0) {
        int wid = t >> 5;
        wsum[wid][0] = s0; wsum[wid][1] = s1; wsum[wid][2] = s2; wsum[wid][3] = s3;
    }
    __syncthreads();
    if (t < 4) {
        double acc = 0.0;
#pragma unroll
        for (int w = 0; w < 8; w++) acc += (double)wsum[w][t];
        atomicAdd(&g.stats1[(blockIdx.x & (NBANK - 1)) * BSTRIDE + t], acc);
    }
    __shared__ int last;
    __syncthreads();
    if (t == 0) {
        __threadfence();
        last = (atomicAdd(&g.done1, 1u) == gridDim.x - 1);
    }
    __syncthreads();
    if (last && t < 2) {
        __threadfence();
        double sum = 0.0, sumsq = 0.0;
#pragma unroll
        for (int bk = 0; bk < NBANK; bk++) {
            sum   += g.stats1[bk * BSTRIDE + t];
            sumsq += g.stats1[bk * BSTRIDE + 2 + t];
        }
        double invN = 1.0 / (double)N;
        double mu   = sum * invN;
        double var  = sumsq * invN - mu * mu;
        float  sc   = (float)((double)gamma1[t] / sqrt(var + 1e-5));
        g_scale1[t] = sc;
        g_shift1[t] = beta1[t] - (float)mu * sc;
    }
}

// ---------------- conv2: BN1(h1e)[N,2] x W2 -> red.v4 [N,4], 2 edges/thr -----
// shared-weight loop: each sW pair load feeds BOTH edges (16 LDS.128 vs 32)
__global__ void __launch_bounds__(256) k_conv2(
        const void* __restrict__ eidx, const float* __restrict__ attr,
        const float* __restrict__ W2, int E) {
    __shared__ float4 sW[16];     // sW[2b]=W2[b][0][:], sW[2b+1]=W2[b][1][:]
    __shared__ __align__(16) float sAttr[1536];
    __shared__ float  sSc[2], sSh[2];
    __shared__ int    sI64;
    int t = threadIdx.x;
    int base = blockIdx.x * 512;
    if (t < 16) sW[t] = ((const float4*)W2)[t];
    if (t < 2)  { sSc[t] = g_scale1[t]; sSh[t] = g_shift1[t]; }
    if (t == 0) sI64 = sniff64((const unsigned*)eidx, base, E);
    int nEdge = min(512, E - base);
    stage_attr512(attr, base, nEdge, sAttr);

    int le = 2 * t;
    if (le >= nEdge) return;
    int e = base + le;

    if (le + 1 < nEdge) {
        int sA, dA, sB, dB;
        load_edge2(eidx, e, E, sI64, sA, dA, sB, dB);
        float2 hA = *(const float2*)&g_h1e[2 * sA];   // both gathers in flight
        float2 hB = *(const float2*)&g_h1e[2 * sB];
        float fA[3], fB[3], wA[8], wB[8];
        pair_attr(sAttr, t, fA, fB);
        basis8(fA[0], fA[1], fA[2], wA);
        basis8(fB[0], fB[1], fB[2], wB);
        float h0A = fmaf(hA.x, sSc[0], sSh[0]);
        float h1A = fmaf(hA.y, sSc[1], sSh[1]);
        float h0B = fmaf(hB.x, sSc[0], sSh[0]);
        float h1B = fmaf(hB.y, sSc[1], sSh[1]);
        float aA0 = 0.f, aA1 = 0.f, aA2 = 0.f, aA3 = 0.f;
        float aB0 = 0.f, aB1 = 0.f, aB2 = 0.f, aB3 = 0.f;
#pragma unroll
        for (int b = 0; b < 8; b++) {
            float4 A = sW[2 * b];             // one pair of loads, two edges
            float4 B = sW[2 * b + 1];
            float cA = wA[b], cB = wB[b];
            aA0 = fmaf(cA, fmaf(h1A, B.x, h0A * A.x), aA0);
            aA1 = fmaf(cA, fmaf(h1A, B.y, h0A * A.y), aA1);
            aA2 = fmaf(cA, fmaf(h1A, B.z, h0A * A.z), aA2);
            aA3 = fmaf(cA, fmaf(h1A, B.w, h0A * A.w), aA3);
            aB0 = fmaf(cB, fmaf(h1B, B.x, h0B * A.x), aB0);
            aB1 = fmaf(cB, fmaf(h1B, B.y, h0B * A.y), aB1);
            aB2 = fmaf(cB, fmaf(h1B, B.z, h0B * A.z), aB2);
            aB3 = fmaf(cB, fmaf(h1B, B.w, h0B * A.w), aB3);
        }
        asm volatile("red.global.add.v4.f32 [%0], {%1, %2, %3, %4};"
                     :: "l"(&g.h2[4 * dA]), "f"(aA0), "f"(aA1), "f"(aA2), "f"(aA3)
                     : "memory");
        asm volatile("red.global.add.v4.f32 [%0], {%1, %2, %3, %4};"
                     :: "l"(&g.h2[4 * dB]), "f"(aB0), "f"(aB1), "f"(aB2), "f"(aB3)
                     : "memory");
    } else {
        int src, dst;
        load_edge1(eidx, e, E, sI64, src, dst);
        float2 hv = *(const float2*)&g_h1e[2 * src];
        float h0 = fmaf(hv.x, sSc[0], sSh[0]);
        float h1 = fmaf(hv.y, sSc[1], sSh[1]);
        float w[8];
        basis8(sAttr[3*le], sAttr[3*le+1], sAttr[3*le+2], w);
        float acc0 = 0.f, acc1 = 0.f, acc2 = 0.f, acc3 = 0.f;
#pragma unroll
        for (int b = 0; b < 8; b++) {
            float4 A = sW[2 * b];
            float4 B = sW[2 * b + 1];
            float wb = w[b];
            acc0 = fmaf(wb, fmaf(h1, B.x, h0 * A.x), acc0);
            acc1 = fmaf(wb, fmaf(h1, B.y, h0 * A.y), acc1);
            acc2 = fmaf(wb, fmaf(h1, B.z, h0 * A.z), acc2);
            acc3 = fmaf(wb, fmaf(h1, B.w, h0 * A.w), acc3);
        }
        asm volatile("red.global.add.v4.f32 [%0], {%1, %2, %3, %4};"
                     :: "l"(&g.h2[4 * dst]), "f"(acc0), "f"(acc1), "f"(acc2), "f"(acc3)
                     : "memory");
    }
}

// -- finish2: 4 n/t; mean, BN2 stats+params, sign-aware pool, fc last block ---
__global__ void __launch_bounds__(256) k_finish2(
        const float* __restrict__ pos,
        const float* __restrict__ gamma2, const float* __restrict__ beta2,
        const float* __restrict__ fcw, float* __restrict__ out, int N) {
    __shared__ unsigned spool[64];
    __shared__ float    wsum[8][8];
    __shared__ unsigned sNeg;
    int t = threadIdx.x;
    if (t < 64) spool[t] = 0u;
    if (t == 0) {
        unsigned mk = 0;
#pragma unroll
        for (int o = 0; o < 4; o++)
            if (__ldg(&gamma2[o]) < 0.f) mk |= 1u << o;
        sNeg = mk;
    }
    __syncthreads();
    unsigned neg = sNeg;

    int base = blockIdx.x * 1024;
    float s[8] = {0.f,0.f,0.f,0.f,0.f,0.f,0.f,0.f};
#pragma unroll
    for (int k = 0; k < 4; k++) {
        int n = base + t + 256 * k;
        if (n < N) {
            float4 h  = *(const float4*)&g.h2[4 * n];
            float inv = g_inv[n];
            float m0 = h.x * inv, m1 = h.y * inv, m2 = h.z * inv, m3 = h.w * inv;
            float2 p = *(const float2*)&pos[2 * n];
            int cx = min(max((int)floorf(p.x * 0.04f), 0), 3);
            int cy = min(max((int)floorf(p.y * 0.04f), 0), 3);
            int cl = 4 * (cx + 4 * cy);
            unsigned e0 = fenc(m0), e1 = fenc(m1), e2 = fenc(m2), e3 = fenc(m3);
            atomicMax(&spool[cl + 0], (neg & 1u) ? ~e0 : (e0 - REBASE));
            atomicMax(&spool[cl + 1], (neg & 2u) ? ~e1 : (e1 - REBASE));
            atomicMax(&spool[cl + 2], (neg & 4u) ? ~e2 : (e2 - REBASE));
            atomicMax(&spool[cl + 3], (neg & 8u) ? ~e3 : (e3 - REBASE));
            s[0] += m0; s[1] += m1; s[2] += m2; s[3] += m3;
            s[4] += m0 * m0; s[5] += m1 * m1; s[6] += m2 * m2; s[7] += m3 * m3;
        }
    }
#pragma unroll
    for (int o = 16; o; o >>= 1)
#pragma unroll
        for (int k = 0; k < 8; k++) s[k] += __shfl_down_sync(~0u, s[k], o);
    if ((t & 31) == 0) {
        int wid = t >> 5;
#pragma unroll
        for (int k = 0; k < 8; k++) wsum[wid][k] = s[k];
    }
    __syncthreads();
    if (t < 8) {
        double acc = 0.0;
#pragma unroll
        for (int w = 0; w < 8; w++) acc += (double)wsum[w][t];
        atomicAdd(&g.stats2[(blockIdx.x & (NBANK - 1)) * BSTRIDE + t], acc);
    }
    if (t < 64 && spool[t]) atomicMax(&g.pool[t], spool[t]);
    __shared__ int last;
    __syncthreads();
    if (t == 0) {
        __threadfence();
        last = (atomicAdd(&g.done2, 1u) == gridDim.x - 1);
    }
    __syncthreads();
    if (!last) return;

    if (t < 4) {
        __threadfence();
        double sum = 0.0, sumsq = 0.0;
#pragma unroll
        for (int bk = 0; bk < NBANK; bk++) {
            sum   += g.stats2[bk * BSTRIDE + t];
            sumsq += g.stats2[bk * BSTRIDE + 4 + t];
        }
        double invN = 1.0 / (double)N;
        double mu   = sum * invN;
        double var  = sumsq * invN - mu * mu;
        float  sc   = (float)((double)gamma2[t] / sqrt(var + 1e-5));
        g_scale2[t] = sc;
        g_shift2[t] = beta2[t] - (float)mu * sc;
    }
    __syncthreads();

    __shared__ float v[64];
    if (t < 64) {
        int      o   = t & 3;
        unsigned e   = g.pool[t];
        float    val = (neg >> o & 1) ? fdec(~e) : fdec(e + REBASE);
        v[t] = (e == 0u) ? 0.0f : fmaf(val, g_scale2[o], g_shift2[o]);
    }
    __syncthreads();
    if (t < 128) {
        int w = t >> 5, l = t & 31;
        float p = v[l] * fcw[w * 64 + l] + v[l + 32] * fcw[w * 64 + l + 32];
#pragma unroll
        for (int o = 16; o; o >>= 1) p += __shfl_down_sync(~0u, p, o);
        if (l == 0) out[w] = p;
    }
}

// ---------------- host launcher (graph-capturable) ---------------------------
extern "C" void kernel_launch(void* const* d_in, const int* in_sizes, int n_in,
                              void* d_out, int out_size) {
    const float* x      = (const float*)d_in[0];
    const void*  eidx   = d_in[1];
    const float* attr   = (const float*)d_in[2];
    const float* pos    = (const float*)d_in[3];
    const float* W1     = (const float*)d_in[4];
    const float* W2     = (const float*)d_in[5];
    const float* gamma1 = (const float*)d_in[6];
    const float* beta1  = (const float*)d_in[7];
    const float* gamma2 = (const float*)d_in[8];
    const float* beta2  = (const float*)d_in[9];
    const float* fcw    = (const float*)d_in[10];
    float*       out    = (float*)d_out;

    int N = in_sizes[0];        // x is [N,1]
    int E = in_sizes[2] / 3;    // edge_attr is [E,3]

    void* pg;
    cudaGetSymbolAddress(&pg, g);
    cudaMemsetAsync(pg, 0, sizeof(ScratchT));

    int ebl  = (E + 511) / 512;    // 2 edges/thread
    int nbl4 = (N + 1023) / 1024;  // 4 nodes/thread

    k_conv1<<<ebl, 256>>>(x, eidx, attr, W1, E);
    k_finish1<<<nbl4, 256>>>(gamma1, beta1, N);
    k_conv2<<<ebl, 256>>>(eidx, attr, W2, E);
    k_finish2<<<nbl4, 256>>>(pos, gamma2, beta2, fcw, out, N);
}

// round 17
// speedup vs baseline: 1.2547x; 1.0038x over previous
#include <cuda_runtime.h>
#include <math.h>
#include <stdint.h>

#define NMAX 262144
#define NBANK 16
#define BSTRIDE 32   // doubles per bank (256B stride: no L2 hash pair-collide)

// ---------------- scratch (device globals; single zero-memset) ---------------
struct ScratchT {
    float    h1[4 * NMAX];            // conv1 accum: h0, h1, cnt, pad
    float    h2[4 * NMAX];            // conv2 accum: 4 channels
    double   stats1[NBANK * BSTRIDE]; // banked: [b]: s0,s1,sq0,sq1
    double   stats2[NBANK * BSTRIDE]; // banked: [b]: s0..s3, sq0..sq3
    unsigned done1, done2;            // last-block counters
    unsigned pool[64];                // sign-aware ordered-uint, 0 == empty
};
__device__ ScratchT g;
__device__ float    g_h1e[2 * NMAX];  // elu(mean(h1)) packed float2
__device__ float    g_inv[NMAX];      // 1 / max(cnt,1)
__device__ float    g_scale1[2], g_shift1[2];
__device__ float    g_scale2[4], g_shift2[4];

// ordered-uint encoding: unsigned compare == float compare
__device__ __forceinline__ unsigned fenc(float f) {
    unsigned u = __float_as_uint(f);
    return (u & 0x80000000u) ? ~u : (u | 0x80000000u);
}
__device__ __forceinline__ float fdec(unsigned u) {
    return (u & 0x80000000u) ? __uint_as_float(u & 0x7FFFFFFFu)
                             : __uint_as_float(~u);
}
#define REBASE 0x007FFFFFu   // fenc(-inf): re-base so 0 marks "empty"

// ---------------- trilinear basis weights (pseudo in [0,1): lo==0) -----------
__device__ __forceinline__ void basis8(float f0, float f1, float f2, float* w) {
    float gr0 = 1.f - f0, gr1 = 1.f - f1, gr2 = 1.f - f2;
    float a00 = gr0 * gr1, a10 = f0 * gr1, a01 = gr0 * f1, a11 = f0 * f1;
    w[0] = a00 * gr2; w[1] = a10 * gr2; w[2] = a01 * gr2; w[3] = a11 * gr2;
    w[4] = a00 * f2;  w[5] = a10 * f2;  w[6] = a01 * f2;  w[7] = a11 * f2;
}

// per-block idx-dtype sniff: odd 32-bit words all zero over 8 samples => int64
__device__ __forceinline__ int sniff64(const unsigned* w, int base, int E) {
    unsigned orv = 0;
#pragma unroll
    for (int i = 0; i < 8; i++) {
        int e = base + i;
        if (e < E) orv |= w[2 * e + 1];
    }
    return orv == 0u;
}

// paired index load for edges (e, e+1), e even
__device__ __forceinline__ void load_edge2(const void* eidx, int e, int E, int is64,
                                           int& sA, int& dA, int& sB, int& dB) {
    if (is64) {
        const longlong2* p = (const longlong2*)eidx;
        longlong2 s = __ldg(&p[e >> 1]);
        longlong2 d = __ldg(&p[(size_t)(E >> 1) + (e >> 1)]);
        sA = (int)s.x; sB = (int)s.y; dA = (int)d.x; dB = (int)d.y;
    } else {
        const int2* p = (const int2*)eidx;
        int2 s = __ldg(&p[e >> 1]);
        int2 d = __ldg(&p[(E >> 1) + (e >> 1)]);
        sA = s.x; sB = s.y; dA = d.x; dB = d.y;
    }
}
__device__ __forceinline__ void load_edge1(const void* eidx, int e, int E, int is64,
                                           int& src, int& dst) {
    if (is64) {
        const long long* p = (const long long*)eidx;
        src = (int)__ldg(&p[e]);
        dst = (int)__ldg(&p[(size_t)E + e]);
    } else {
        const int* p = (const int*)eidx;
        src = __ldg(&p[e]);
        dst = __ldg(&p[E + e]);
    }
}

// stage 512 edges' attr (1536 floats) into smem via coalesced float4 loads
__device__ __forceinline__ void stage_attr512(const float* __restrict__ attr,
                                              int base, int nEdge, float* sAttr) {
    int t = threadIdx.x;
    if (nEdge == 512) {
        const float4* a4 = (const float4*)attr;
        int g0 = (3 * base) >> 2;
#pragma unroll
        for (int i = 0; i < 2; i++) {
            int k = t + 256 * i;
            if (k < 384) *(float4*)&sAttr[4 * k] = __ldg(&a4[g0 + k]);
        }
    } else {
        for (int i = t; i < 3 * nEdge; i += 256)
            sAttr[i] = __ldg(&attr[3 * base + i]);
    }
    __syncthreads();
}

// read edge-pair attr via 3x LDS.64
__device__ __forceinline__ void pair_attr(const float* sAttr, int t,
                                          float* fA, float* fB) {
    const float2* s2 = (const float2*)sAttr;
    float2 p0 = s2[3 * t], p1 = s2[3 * t + 1], p2 = s2[3 * t + 2];
    fA[0] = p0.x; fA[1] = p0.y; fA[2] = p1.x;
    fB[0] = p1.y; fB[1] = p2.x; fB[2] = p2.y;
}

// ---------------- conv1: x[N,1] x W1 -> red.v4 (h0,h1,cnt,0), 2 edges/thr ----
__global__ void __launch_bounds__(256) k_conv1(
        const float* __restrict__ x, const void* __restrict__ eidx,
        const float* __restrict__ attr, const float* __restrict__ W1, int E) {
    __shared__ float2 sW[8];
    __shared__ __align__(16) float sAttr[1536];
    __shared__ int    sI64;
    int t = threadIdx.x;
    int base = blockIdx.x * 512;
    if (t < 8) sW[t] = ((const float2*)W1)[t];
    if (t == 0) sI64 = sniff64((const unsigned*)eidx, base, E);
    int nEdge = min(512, E - base);
    stage_attr512(attr, base, nEdge, sAttr);

    int le = 2 * t;
    if (le >= nEdge) return;
    int e = base + le;

    if (le + 1 < nEdge) {
        int sA, dA, sB, dB;
        load_edge2(eidx, e, E, sI64, sA, dA, sB, dB);
        float xA = __ldg(&x[sA]);
        float xB = __ldg(&x[sB]);
        float fA[3], fB[3], wA[8], wB[8];
        pair_attr(sAttr, t, fA, fB);
        basis8(fA[0], fA[1], fA[2], wA);
        basis8(fB[0], fB[1], fB[2], wB);
        float a0 = 0.f, a1 = 0.f, b0 = 0.f, b1 = 0.f;
#pragma unroll
        for (int b = 0; b < 8; b++) {
            float2 W = sW[b];
            a0 = fmaf(wA[b], W.x, a0); a1 = fmaf(wA[b], W.y, a1);
            b0 = fmaf(wB[b], W.x, b0); b1 = fmaf(wB[b], W.y, b1);
        }
        a0 *= xA; a1 *= xA; b0 *= xB; b1 *= xB;
        asm volatile("red.global.add.v4.f32 [%0], {%1, %2, %3, %4};"
                     :: "l"(&g.h1[4 * dA]), "f"(a0), "f"(a1), "f"(1.0f), "f"(0.0f) : "memory");
        asm volatile("red.global.add.v4.f32 [%0], {%1, %2, %3, %4};"
                     :: "l"(&g.h1[4 * dB]), "f"(b0), "f"(b1), "f"(1.0f), "f"(0.0f) : "memory");
    } else {
        int src, dst;
        load_edge1(eidx, e, E, sI64, src, dst);
        float w[8];
        basis8(sAttr[3*le], sAttr[3*le+1], sAttr[3*le+2], w);
        float a0 = 0.f, a1 = 0.f;
#pragma unroll
        for (int b = 0; b < 8; b++) { float2 W = sW[b]; a0 = fmaf(w[b], W.x, a0); a1 = fmaf(w[b], W.y, a1); }
        float xs = __ldg(&x[src]);
        a0 *= xs; a1 *= xs;
        asm volatile("red.global.add.v4.f32 [%0], {%1, %2, %3, %4};"
                     :: "l"(&g.h1[4 * dst]), "f"(a0), "f"(a1), "f"(1.0f), "f"(0.0f) : "memory");
    }
}

// ---------------- finish1: 4 nodes/thread, mean->ELU->store, BN1 stats -------
__global__ void __launch_bounds__(256) k_finish1(
        const float* __restrict__ gamma1, const float* __restrict__ beta1, int N) {
    __shared__ float wsum[8][4];
    int t = threadIdx.x;
    int base = blockIdx.x * 1024;
    float s0 = 0.f, s1 = 0.f, s2 = 0.f, s3 = 0.f;
#pragma unroll
    for (int k = 0; k < 4; k++) {
        int n = base + t + 256 * k;
        if (n < N) {
            float4 h  = *(const float4*)&g.h1[4 * n];
            float inv = 1.0f / fmaxf(h.z, 1.0f);
            g_inv[n] = inv;
            float a = h.x * inv, b = h.y * inv;
            a = (a > 0.f) ? a : expm1f(a);
            b = (b > 0.f) ? b : expm1f(b);
            *(float2*)&g_h1e[2 * n] = make_float2(a, b);
            s0 += a; s1 += b; s2 += a * a; s3 += b * b;
        }
    }
#pragma unroll
    for (int o = 16; o; o >>= 1) {
        s0 += __shfl_down_sync(~0u, s0, o);
        s1 += __shfl_down_sync(~0u, s1, o);
        s2 += __shfl_down_sync(~0u, s2, o);
        s3 += __shfl_down_sync(~0u, s3, o);
    }
    if ((t & 31) == 0) {
        int wid = t >> 5;
        wsum[wid][0] = s0; wsum[wid][1] = s1; wsum[wid][2] = s2; wsum[wid][3] = s3;
    }
    __syncthreads();
    if (t < 4) {
        double acc = 0.0;
#pragma unroll
        for (int w = 0; w < 8; w++) acc += (double)wsum[w][t];
        atomicAdd(&g.stats1[(blockIdx.x & (NBANK - 1)) * BSTRIDE + t], acc);
    }
    __shared__ int last;
    __syncthreads();
    if (t == 0) {
        __threadfence();
        last = (atomicAdd(&g.done1, 1u) == gridDim.x - 1);
    }
    __syncthreads();
    if (last && t < 2) {
        __threadfence();
        double sum = 0.0, sumsq = 0.0;
#pragma unroll
        for (int bk = 0; bk < NBANK; bk++) {
            sum   += g.stats1[bk * BSTRIDE + t];
            sumsq += g.stats1[bk * BSTRIDE + 2 + t];
        }
        double invN = 1.0 / (double)N;
        double mu   = sum * invN;
        double var  = sumsq * invN - mu * mu;
        float  sc   = (float)((double)gamma1[t] / sqrt(var + 1e-5));
        g_scale1[t] = sc;
        g_shift1[t] = beta1[t] - (float)mu * sc;
    }
}

// ---------------- conv2: BN1(h1e)[N,2] x W2 -> red.v4 [N,4], 2 edges/thr -----
__global__ void __launch_bounds__(256) k_conv2(
        const void* __restrict__ eidx, const float* __restrict__ attr,
        const float* __restrict__ W2, int E) {
    __shared__ float4 sW[16];     // sW[2b]=W2[b][0][:], sW[2b+1]=W2[b][1][:]
    __shared__ __align__(16) float sAttr[1536];
    __shared__ float  sSc[2], sSh[2];
    __shared__ int    sI64;
    int t = threadIdx.x;
    int base = blockIdx.x * 512;
    if (t < 16) sW[t] = ((const float4*)W2)[t];
    if (t < 2)  { sSc[t] = g_scale1[t]; sSh[t] = g_shift1[t]; }
    if (t == 0) sI64 = sniff64((const unsigned*)eidx, base, E);
    int nEdge = min(512, E - base);
    stage_attr512(attr, base, nEdge, sAttr);

    int le = 2 * t;
    if (le >= nEdge) return;
    int e = base + le;

    if (le + 1 < nEdge) {
        int sA, dA, sB, dB;
        load_edge2(eidx, e, E, sI64, sA, dA, sB, dB);
        float2 hA = *(const float2*)&g_h1e[2 * sA];   // both gathers in flight
        float2 hB = *(const float2*)&g_h1e[2 * sB];
        float fA[3], fB[3], wA[8], wB[8];
        pair_attr(sAttr, t, fA, fB);
        basis8(fA[0], fA[1], fA[2], wA);
        basis8(fB[0], fB[1], fB[2], wB);
        float h0A = fmaf(hA.x, sSc[0], sSh[0]);
        float h1A = fmaf(hA.y, sSc[1], sSh[1]);
        float h0B = fmaf(hB.x, sSc[0], sSh[0]);
        float h1B = fmaf(hB.y, sSc[1], sSh[1]);
        float aA0 = 0.f, aA1 = 0.f, aA2 = 0.f, aA3 = 0.f;
        float aB0 = 0.f, aB1 = 0.f, aB2 = 0.f, aB3 = 0.f;
#pragma unroll
        for (int b = 0; b < 8; b++) {
            float4 A = sW[2 * b];
            float4 B = sW[2 * b + 1];
            float cA = wA[b], cB = wB[b];
            aA0 = fmaf(cA, fmaf(h1A, B.x, h0A * A.x), aA0);
            aA1 = fmaf(cA, fmaf(h1A, B.y, h0A * A.y), aA1);
            aA2 = fmaf(cA, fmaf(h1A, B.z, h0A * A.z), aA2);
            aA3 = fmaf(cA, fmaf(h1A, B.w, h0A * A.w), aA3);
            aB0 = fmaf(cB, fmaf(h1B, B.x, h0B * A.x), aB0);
            aB1 = fmaf(cB, fmaf(h1B, B.y, h0B * A.y), aB1);
            aB2 = fmaf(cB, fmaf(h1B, B.z, h0B * A.z), aB2);
            aB3 = fmaf(cB, fmaf(h1B, B.w, h0B * A.w), aB3);
        }
        asm volatile("red.global.add.v4.f32 [%0], {%1, %2, %3, %4};"
                     :: "l"(&g.h2[4 * dA]), "f"(aA0), "f"(aA1), "f"(aA2), "f"(aA3)
                     : "memory");
        asm volatile("red.global.add.v4.f32 [%0], {%1, %2, %3, %4};"
                     :: "l"(&g.h2[4 * dB]), "f"(aB0), "f"(aB1), "f"(aB2), "f"(aB3)
                     : "memory");
    } else {
        int src, dst;
        load_edge1(eidx, e, E, sI64, src, dst);
        float2 hv = *(const float2*)&g_h1e[2 * src];
        float h0 = fmaf(hv.x, sSc[0], sSh[0]);
        float h1 = fmaf(hv.y, sSc[1], sSh[1]);
        float w[8];
        basis8(sAttr[3*le], sAttr[3*le+1], sAttr[3*le+2], w);
        float acc0 = 0.f, acc1 = 0.f, acc2 = 0.f, acc3 = 0.f;
#pragma unroll
        for (int b = 0; b < 8; b++) {
            float4 A = sW[2 * b];
            float4 B = sW[2 * b + 1];
            float wb = w[b];
            acc0 = fmaf(wb, fmaf(h1, B.x, h0 * A.x), acc0);
            acc1 = fmaf(wb, fmaf(h1, B.y, h0 * A.y), acc1);
            acc2 = fmaf(wb, fmaf(h1, B.z, h0 * A.z), acc2);
            acc3 = fmaf(wb, fmaf(h1, B.w, h0 * A.w), acc3);
        }
        asm volatile("red.global.add.v4.f32 [%0], {%1, %2, %3, %4};"
                     :: "l"(&g.h2[4 * dst]), "f"(acc0), "f"(acc1), "f"(acc2), "f"(acc3)
                     : "memory");
    }
}

// -- finish2: 4 n/t; warp-private pool, BN2 stats+params, fc last block -------
__global__ void __launch_bounds__(256) k_finish2(
        const float* __restrict__ pos,
        const float* __restrict__ gamma2, const float* __restrict__ beta2,
        const float* __restrict__ fcw, float* __restrict__ out, int N) {
    __shared__ unsigned spool[8][64];   // per-warp private pool banks
    __shared__ float    wsum[8][8];
    __shared__ unsigned sNeg;
    int t = threadIdx.x;
    int wid = t >> 5;
#pragma unroll
    for (int i = 0; i < 2; i++) ((unsigned*)spool)[t + 256 * i] = 0u;
    if (t == 0) {
        unsigned mk = 0;
#pragma unroll
        for (int o = 0; o < 4; o++)
            if (__ldg(&gamma2[o]) < 0.f) mk |= 1u << o;
        sNeg = mk;
    }
    __syncthreads();
    unsigned neg = sNeg;
    unsigned* mypool = spool[wid];

    int base = blockIdx.x * 1024;
    float s[8] = {0.f,0.f,0.f,0.f,0.f,0.f,0.f,0.f};
#pragma unroll
    for (int k = 0; k < 4; k++) {
        int n = base + t + 256 * k;
        if (n < N) {
            float4 h  = *(const float4*)&g.h2[4 * n];
            float inv = g_inv[n];
            float m0 = h.x * inv, m1 = h.y * inv, m2 = h.z * inv, m3 = h.w * inv;
            float2 p = *(const float2*)&pos[2 * n];
            int cx = min(max((int)floorf(p.x * 0.04f), 0), 3);
            int cy = min(max((int)floorf(p.y * 0.04f), 0), 3);
            int cl = 4 * (cx + 4 * cy);
            unsigned e0 = fenc(m0), e1 = fenc(m1), e2 = fenc(m2), e3 = fenc(m3);
            atomicMax(&mypool[cl + 0], (neg & 1u) ? ~e0 : (e0 - REBASE));
            atomicMax(&mypool[cl + 1], (neg & 2u) ? ~e1 : (e1 - REBASE));
            atomicMax(&mypool[cl + 2], (neg & 4u) ? ~e2 : (e2 - REBASE));
            atomicMax(&mypool[cl + 3], (neg & 8u) ? ~e3 : (e3 - REBASE));
            s[0] += m0; s[1] += m1; s[2] += m2; s[3] += m3;
            s[4] += m0 * m0; s[5] += m1 * m1; s[6] += m2 * m2; s[7] += m3 * m3;
        }
    }
#pragma unroll
    for (int o = 16; o; o >>= 1)
#pragma unroll
        for (int k = 0; k < 8; k++) s[k] += __shfl_down_sync(~0u, s[k], o);
    if ((t & 31) == 0) {
#pragma unroll
        for (int k = 0; k < 8; k++) wsum[wid][k] = s[k];
    }
    __syncthreads();
    if (t < 8) {
        double acc = 0.0;
#pragma unroll
        for (int w = 0; w < 8; w++) acc += (double)wsum[w][t];
        atomicAdd(&g.stats2[(blockIdx.x & (NBANK - 1)) * BSTRIDE + t], acc);
    }
    if (t < 64) {                       // combine warp banks, one global RMW
        unsigned m = spool[0][t];
#pragma unroll
        for (int w = 1; w < 8; w++) m = max(m, spool[w][t]);
        if (m) atomicMax(&g.pool[t], m);
    }
    __shared__ int last;
    __syncthreads();
    if (t == 0)   // all prior publishes are L2 atomics (globally coherent); no fence needed
        last = (atomicAdd(&g.done2, 1u) == gridDim.x - 1);
    __syncthreads();
    if (!last) return;

    if (t < 4) {
        __threadfence();
        double sum = 0.0, sumsq = 0.0;
#pragma unroll
        for (int bk = 0; bk < NBANK; bk++) {
            sum   += g.stats2[bk * BSTRIDE + t];
            sumsq += g.stats2[bk * BSTRIDE + 4 + t];
        }
        double invN = 1.0 / (double)N;
        double mu   = sum * invN;
        double var  = sumsq * invN - mu * mu;
        float  sc   = (float)((double)gamma2[t] / sqrt(var + 1e-5));
        g_scale2[t] = sc;
        g_shift2[t] = beta2[t] - (float)mu * sc;
    }
    __syncthreads();

    __shared__ float v[64];
    if (t < 64) {
        int      o   = t & 3;
        unsigned e   = g.pool[t];
        float    val = (neg >> o & 1) ? fdec(~e) : fdec(e + REBASE);
        v[t] = (e == 0u) ? 0.0f : fmaf(val, g_scale2[o], g_shift2[o]);
    }
    __syncthreads();
    if (t < 128) {
        int w = t >> 5, l = t & 31;
        float p = v[l] * fcw[w * 64 + l] + v[l + 32] * fcw[w * 64 + l + 32];
#pragma unroll
        for (int o = 16; o; o >>= 1) p += __shfl_down_sync(~0u, p, o);
        if (l == 0) out[w] = p;
    }
}

// ---------------- host launcher (graph-capturable) ---------------------------
extern "C" void kernel_launch(void* const* d_in, const int* in_sizes, int n_in,
                              void* d_out, int out_size) {
    const float* x      = (const float*)d_in[0];
    const void*  eidx   = d_in[1];
    const float* attr   = (const float*)d_in[2];
    const float* pos    = (const float*)d_in[3];
    const float* W1     = (const float*)d_in[4];
    const float* W2     = (const float*)d_in[5];
    const float* gamma1 = (const float*)d_in[6];
    const float* beta1  = (const float*)d_in[7];
    const float* gamma2 = (const float*)d_in[8];
    const float* beta2  = (const float*)d_in[9];
    const float* fcw    = (const float*)d_in[10];
    float*       out    = (float*)d_out;

    int N = in_sizes[0];        // x is [N,1]
    int E = in_sizes[2] / 3;    // edge_attr is [E,3]

    void* pg;
    cudaGetSymbolAddress(&pg, g);
    cudaMemsetAsync(pg, 0, sizeof(ScratchT));

    int ebl  = (E + 511) / 512;    // 2 edges/thread
    int nbl4 = (N + 1023) / 1024;  // 4 nodes/thread

    k_conv1<<<ebl, 256>>>(x, eidx, attr, W1, E);
    k_finish1<<<nbl4, 256>>>(gamma1, beta1, N);
    k_conv2<<<ebl, 256>>>(eidx, attr, W2, E);
    k_finish2<<<nbl4, 256>>>(pos, gamma2, beta2, fcw, out, N);
}